// round 13
// baseline (speedup 1.0000x reference)
#include <cuda_runtime.h>
#include <cuda_bf16.h>
#include <math.h>
#include <stdint.h>

// Problem shape (fixed)
#define B_  32
#define Ls  512
#define D_  768
#define Kp  8192
#define M_  (B_ * Ls)        // 16384

// ---------------- device scratch (allocation-free) -------------------------
__device__ float g_logits[(size_t)M_ * Kp];           // fp32 logits (compact rows)
__device__ float g_c[M_];                             // per-row m + log(sum exp)
__device__ __nv_bfloat16 g_Qh[(size_t)M_ * D_];
__device__ __nv_bfloat16 g_Ql[(size_t)M_ * D_];
__device__ __nv_bfloat16 g_Ph[(size_t)Kp * D_];
__device__ __nv_bfloat16 g_Pl[(size_t)Kp * D_];
__device__ int g_cnt[B_];
__device__ int g_local[M_];
__device__ int g_off[B_ + 2];        // [0..32] offsets; [32]=valid; [33]=padded
__device__ int g_rowidx[M_];

// ---------------- PTX helpers ------------------------------------------------
__device__ __forceinline__ uint32_t smem_u32(const void* p) {
    uint32_t a;
    asm("{ .reg .u64 t; cvta.to.shared.u64 t, %1; cvt.u32.u64 %0, t; }"
        : "=r"(a) : "l"(p));
    return a;
}
__device__ __forceinline__ void cp16(uint32_t dst, const void* src) {
    asm volatile("cp.async.cg.shared.global [%0], [%1], 16;" :: "r"(dst), "l"(src));
}
__device__ __forceinline__ void cp_commit() {
    asm volatile("cp.async.commit_group;" ::: "memory");
}
__device__ __forceinline__ void ldm_x4(uint32_t* r, uint32_t addr) {
    asm volatile("ldmatrix.sync.aligned.m8n8.x4.shared.b16 {%0,%1,%2,%3}, [%4];"
                 : "=r"(r[0]), "=r"(r[1]), "=r"(r[2]), "=r"(r[3]) : "r"(addr));
}
__device__ __forceinline__ void mma16816(float* c, const uint32_t* a, const uint32_t* b) {
    asm volatile(
        "mma.sync.aligned.m16n8k16.row.col.f32.bf16.bf16.f32 "
        "{%0,%1,%2,%3}, {%4,%5,%6,%7}, {%8,%9}, {%0,%1,%2,%3};"
        : "+f"(c[0]), "+f"(c[1]), "+f"(c[2]), "+f"(c[3])
        : "r"(a[0]), "r"(a[1]), "r"(a[2]), "r"(a[3]), "r"(b[0]), "r"(b[1]));
}

// ---------------- mask compaction -------------------------------------------
__global__ __launch_bounds__(Ls)
void mask_scan(const int* __restrict__ mask)
{
    const int b = blockIdx.x, l = threadIdx.x;
    const int lane = l & 31, w = l >> 5;
    const int v = mask[b * Ls + l] ? 1 : 0;
    const unsigned bal = __ballot_sync(0xffffffffu, v);
    const int pre = __popc(bal & ((1u << lane) - 1u));
    __shared__ int ws[16];
    if (lane == 0) ws[w] = __popc(bal);
    __syncthreads();
    int woff = 0;
#pragma unroll
    for (int i = 0; i < 16; i++) woff += (i < w) ? ws[i] : 0;
    g_local[b * Ls + l] = woff + pre;
    if (l == Ls - 1) g_cnt[b] = woff + pre + v;
}

__global__ void scan_offsets()
{
    const int t = threadIdx.x;            // 0..31
    int x = g_cnt[t];
#pragma unroll
    for (int o = 1; o < 32; o <<= 1) {
        int y = __shfl_up_sync(0xffffffffu, x, o);
        if (t >= o) x += y;
    }
    g_off[t + 1] = x;
    if (t == 0) g_off[0] = 0;
    if (t == 31) g_off[B_ + 1] = (x + 127) & ~127;   // padded total (TILE_M=128)
}

__global__ __launch_bounds__(Ls)
void scatter_idx(const int* __restrict__ mask)
{
    const int b = blockIdx.x, l = threadIdx.x;
    if (mask[b * Ls + l])
        g_rowidx[g_off[b] + g_local[b * Ls + l]] = b * Ls + l;
}

// ---------------- split Q (gather, 1/temp folded) + split P ----------------
__global__ __launch_bounds__(256)
void splitQ(const float* __restrict__ Q, const float* __restrict__ temp)
{
    const int cr = blockIdx.x;
    const int valid  = g_off[B_];
    const int padded = g_off[B_ + 1];
    if (cr >= padded) return;
    const int tid = threadIdx.x;
    __nv_bfloat16* hp = g_Qh + (size_t)cr * D_;
    __nv_bfloat16* lp = g_Ql + (size_t)cr * D_;
    if (cr >= valid) {
#pragma unroll
        for (int j = 0; j < 3; j++) {
            hp[tid + j * 256] = __float2bfloat16(0.f);
            lp[tid + j * 256] = __float2bfloat16(0.f);
        }
        return;
    }
    const float invT = 1.0f / temp[0];
    const float* src = Q + (size_t)g_rowidx[cr] * D_;
#pragma unroll
    for (int j = 0; j < 3; j++) {
        float v = src[tid + j * 256] * invT;
        __nv_bfloat16 h = __float2bfloat16(v);
        hp[tid + j * 256] = h;
        lp[tid + j * 256] = __float2bfloat16(v - __bfloat162float(h));
    }
}

__global__ __launch_bounds__(256)
void splitP(const float* __restrict__ src, int n)
{
    int i = blockIdx.x * 256 + threadIdx.x;
    if (i < n) {
        float v = src[i];
        __nv_bfloat16 h = __float2bfloat16(v);
        g_Ph[i] = h;
        g_Pl[i] = __float2bfloat16(v - __bfloat162float(h));
    }
}

// ---------------- HMMA GEMM (R7 proven config, m-chunked) -------------------
#define TILE_M 128
#define TILE_N 128
#define BK     32
#define CHUNKS (D_ / BK)       // 24
#define RSTRIDE 40
#define ROWB    (RSTRIDE * 2)
#define TILE_BYTES (128 * ROWB)             // 10240
#define STAGE_BYTES (4 * TILE_BYTES)        // Ah, Al, Bh, Bl
#define SMEM_GEMM   (2 * STAGE_BYTES)       // 81920

__global__ __launch_bounds__(256, 2)
void gemm_mma(int mt0)
{
    const int mtile = mt0 + blockIdx.x;
    if (mtile * TILE_M >= g_off[B_ + 1]) return;

    extern __shared__ __align__(16) char smem[];
    const uint32_t sb = smem_u32(smem);

    const int tid  = threadIdx.x;
    const int wid  = tid >> 5, lane = tid & 31;
    const int wm   = wid & 1;
    const int wn   = wid >> 1;
    const int m0   = mtile * TILE_M;
    const int n0   = blockIdx.y * TILE_N;

    auto load_chunk = [&](int c) {
        const uint32_t stage = sb + (uint32_t)(c & 1) * STAGE_BYTES;
        const int kd0 = c * BK;
#pragma unroll
        for (int it = 0; it < 8; it++) {
            int i    = tid + it * 256;
            int tile = i >> 9;                  // 0:Ah 1:Al 2:Bh 3:Bl
            int r    = (i >> 2) & 127;
            int q    = i & 3;
            uint32_t dst = stage + (uint32_t)tile * TILE_BYTES + r * ROWB + q * 16;
            size_t ge = (size_t)((tile < 2 ? m0 : n0) + r) * D_ + kd0 + q * 8;
            const __nv_bfloat16* src =
                tile == 0 ? g_Qh : tile == 1 ? g_Ql : tile == 2 ? g_Ph : g_Pl;
            cp16(dst, src + ge);
        }
        cp_commit();
    };

    float acc[4][4][4];
#pragma unroll
    for (int i = 0; i < 4; i++)
#pragma unroll
        for (int j = 0; j < 4; j++)
#pragma unroll
            for (int v = 0; v < 4; v++) acc[i][j][v] = 0.f;

    load_chunk(0);
    load_chunk(1);

    for (int c = 0; c < CHUNKS; c++) {
        if (c + 1 < CHUNKS)
            asm volatile("cp.async.wait_group 1;" ::: "memory");
        else
            asm volatile("cp.async.wait_group 0;" ::: "memory");
        __syncthreads();

        const uint32_t stage = sb + (uint32_t)(c & 1) * STAGE_BYTES;
        const uint32_t Ah = stage;
        const uint32_t Al = stage + TILE_BYTES;
        const uint32_t Bh = stage + 2 * TILE_BYTES;
        const uint32_t Bl = stage + 3 * TILE_BYTES;

#pragma unroll
        for (int k16 = 0; k16 < BK; k16 += 16) {
            uint32_t boff = (uint32_t)((wn * 32 + ((lane >> 4) << 3) + (lane & 7)) * ROWB
                                       + (k16 + (((lane >> 3) & 1) << 3)) * 2);
            uint32_t bh[8], bl[8];
            ldm_x4(&bh[0], Bh + boff);
            ldm_x4(&bh[4], Bh + boff + 16 * ROWB);
            ldm_x4(&bl[0], Bl + boff);
            ldm_x4(&bl[4], Bl + boff + 16 * ROWB);

            uint32_t aoff = (uint32_t)((wm * 64 + (lane & 15)) * ROWB
                                       + (k16 + ((lane >> 4) << 3)) * 2);
#pragma unroll
            for (int mt = 0; mt < 4; mt++) {
                uint32_t ah[4], al[4];
                ldm_x4(ah, Ah + aoff + mt * 16 * ROWB);
                ldm_x4(al, Al + aoff + mt * 16 * ROWB);
#pragma unroll
                for (int nt = 0; nt < 4; nt++) {
                    mma16816(acc[mt][nt], ah, &bh[nt * 2]);
                    mma16816(acc[mt][nt], ah, &bl[nt * 2]);
                    mma16816(acc[mt][nt], al, &bh[nt * 2]);
                }
            }
        }
        __syncthreads();
        if (c + 2 < CHUNKS) load_chunk(c + 2);
    }

    const int rbase = m0 + wm * 64 + (lane >> 2);
    const int cbase = n0 + wn * 32 + (lane & 3) * 2;
#pragma unroll
    for (int mt = 0; mt < 4; mt++) {
#pragma unroll
        for (int nt = 0; nt < 4; nt++) {
            float* p0 = &g_logits[(size_t)(rbase + mt * 16) * Kp + cbase + nt * 8];
            float* p1 = &g_logits[(size_t)(rbase + mt * 16 + 8) * Kp + cbase + nt * 8];
            *reinterpret_cast<float2*>(p0) = make_float2(acc[mt][nt][0], acc[mt][nt][1]);
            *reinterpret_cast<float2*>(p1) = make_float2(acc[mt][nt][2], acc[mt][nt][3]);
        }
    }
}

// ---------------- single-pass online row stats (row-chunked) ----------------
__global__ __launch_bounds__(256)
void row_stats(int row0)
{
    const int row = row0 + blockIdx.x;
    if (row >= g_off[B_]) return;
    const float* Lr = g_logits + (size_t)row * Kp;
    const int tid = threadIdx.x;

    float m = -INFINITY, s = 0.f;
#pragma unroll
    for (int j = 0; j < 8; j++) {
        float4 v = *reinterpret_cast<const float4*>(&Lr[(tid + j * 256) * 4]);
        float lm = fmaxf(fmaxf(v.x, v.y), fmaxf(v.z, v.w));
        if (lm > m) { s *= expf(m - lm); m = lm; }
        s += expf(v.x - m) + expf(v.y - m) + expf(v.z - m) + expf(v.w - m);
    }
#pragma unroll
    for (int off = 16; off; off >>= 1) {
        float om = __shfl_xor_sync(0xffffffffu, m, off);
        float os = __shfl_xor_sync(0xffffffffu, s, off);
        float nm = fmaxf(m, om);
        s = s * expf(m - nm) + os * expf(om - nm);
        m = nm;
    }
    __shared__ float shm[8], shs[8];
    if ((tid & 31) == 0) { shm[tid >> 5] = m; shs[tid >> 5] = s; }
    __syncthreads();
    if (tid == 0) {
        float fm = shm[0], fs = shs[0];
#pragma unroll
        for (int w = 1; w < 8; w++) {
            float nm = fmaxf(fm, shm[w]);
            fs = fs * expf(fm - nm) + shs[w] * expf(shm[w] - nm);
            fm = nm;
        }
        g_c[row] = fm + logf(fs);
    }
}

// ---------------- column max over valid rows (batch-chunked) ----------------
__global__ __launch_bounds__(256)
void col_max(float* __restrict__ out, int b0)
{
    const int b   = b0 + blockIdx.y;
    const int k   = blockIdx.x * 256 + threadIdx.x;
    const int tid = threadIdx.x;
    const int lo  = g_off[b], hi = g_off[b + 1];
    const int cnt = hi - lo;

    __shared__ float cs[Ls];
    for (int i = tid; i < cnt; i += 256) cs[i] = g_c[lo + i];
    __syncthreads();

    const float* base = g_logits + (size_t)lo * Kp + k;
    float t = -INFINITY;
    for (int i = 0; i < cnt; i++)
        t = fmaxf(t, base[(size_t)i * Kp] - cs[i]);

    out[b * Kp + k] = (cnt > 0) ? expf(t) : 0.f;
}

// ---------------- L2 normalize ----------------------------------------------
__device__ __forceinline__ float warpSum(float v) {
#pragma unroll
    for (int o = 16; o; o >>= 1) v += __shfl_xor_sync(0xffffffffu, v, o);
    return v;
}

__global__ __launch_bounds__(256)
void l2norm(float* __restrict__ out)
{
    const int b = blockIdx.x;
    float* o = out + b * Kp;
    const int tid = threadIdx.x;
    __shared__ float sh[8];
    __shared__ float bc;

    float s = 0.f;
    for (int i = tid; i < Kp; i += 256) { float v = o[i]; s = fmaf(v, v, s); }
    s = warpSum(s);
    if ((tid & 31) == 0) sh[tid >> 5] = s;
    __syncthreads();
    if (tid == 0) {
        float t = 0.f;
#pragma unroll
        for (int w = 0; w < 8; w++) t += sh[w];
        bc = 1.0f / fmaxf(sqrtf(t), 1e-12f);
    }
    __syncthreads();
    const float sc = bc;
    for (int i = tid; i < Kp; i += 256) o[i] *= sc;
}

// ---------------- launch: two-stream overlapped pipeline --------------------
// Handles created once (outside capture). During capture, s1 is FORKED from
// the main stream via evRoot BEFORE any launch on it (required by the
// stream-capture programming model), and JOINED back via evF at the end.
#define MCHUNKS 8
#define MT_PER_CHUNK ((M_ / TILE_M) / MCHUNKS)     // 16 m-tiles per chunk
#define ROWS_PER_CHUNK (MT_PER_CHUNK * TILE_M)     // 2048 rows

static cudaStream_t s1;
static cudaEvent_t evRoot, evP, evF, evG[MCHUNKS];
static bool inited = false;

extern "C" void kernel_launch(void* const* d_in, const int* in_sizes, int n_in,
                              void* d_out, int out_size)
{
    const float* Q    = (const float*)d_in[0];
    const float* P    = (const float*)d_in[1];
    const float* temp = (const float*)d_in[2];
    const int*   mask = (const int*)d_in[3];
    float* out = (float*)d_out;

    if (!inited) {
        cudaFuncSetAttribute(gemm_mma, cudaFuncAttributeMaxDynamicSharedMemorySize,
                             SMEM_GEMM);
        cudaStreamCreateWithFlags(&s1, cudaStreamNonBlocking);
        cudaEventCreateWithFlags(&evRoot, cudaEventDisableTiming);
        cudaEventCreateWithFlags(&evP, cudaEventDisableTiming);
        cudaEventCreateWithFlags(&evF, cudaEventDisableTiming);
        for (int c = 0; c < MCHUNKS; c++)
            cudaEventCreateWithFlags(&evG[c], cudaEventDisableTiming);
        inited = true;
    }

    // ---- fork s1 from the main stream (required before any s1 launch) ----
    cudaEventRecord(evRoot, 0);
    cudaStreamWaitEvent(s1, evRoot, 0);

    // splitP (independent of mask chain) on side stream
    const int nP = Kp * D_;
    splitP<<<(nP + 255) / 256, 256, 0, s1>>>(P, nP);
    cudaEventRecord(evP, s1);

    // mask chain + Q split on main stream
    mask_scan<<<B_, Ls>>>(mask);
    scan_offsets<<<1, 32>>>();
    scatter_idx<<<B_, Ls>>>(mask);
    splitQ<<<M_, 256>>>(Q, temp);

    cudaStreamWaitEvent(0, evP, 0);      // GEMM needs P splits

    for (int c = 0; c < MCHUNKS; c++) {
        gemm_mma<<<dim3(MT_PER_CHUNK, Kp / TILE_N), 256, SMEM_GEMM>>>(c * MT_PER_CHUNK);
        cudaEventRecord(evG[c], 0);
        cudaStreamWaitEvent(s1, evG[c], 0);
        row_stats<<<ROWS_PER_CHUNK, 256, 0, s1>>>(c * ROWS_PER_CHUNK);
        // batches 4c..4c+3 are fully covered: off[b+1] <= 512*(b+1) <= 2048*(c+1)
        col_max<<<dim3(Kp / 256, 4), 256, 0, s1>>>(out, 4 * c);
    }
    l2norm<<<B_, 256, 0, s1>>>(out);

    // ---- join s1 back into the main stream ----
    cudaEventRecord(evF, s1);
    cudaStreamWaitEvent(0, evF, 0);
}

// round 14
// speedup vs baseline: 1.6936x; 1.6936x over previous
#include <cuda_runtime.h>
#include <cuda_bf16.h>
#include <math.h>
#include <stdint.h>

// Problem shape (fixed)
#define B_  32
#define Ls  512
#define D_  768
#define Kp  8192
#define M_  (B_ * Ls)        // 16384

// ---------------- device scratch (allocation-free) -------------------------
__device__ float g_logits[(size_t)M_ * Kp];           // fp32 logits (compact rows)
__device__ float g_c[M_];                             // per-row m + log(sum exp)
__device__ __nv_bfloat16 g_Qh[(size_t)M_ * D_];
__device__ __nv_bfloat16 g_Ql[(size_t)M_ * D_];
__device__ __nv_bfloat16 g_Ph[(size_t)Kp * D_];
__device__ __nv_bfloat16 g_Pl[(size_t)Kp * D_];
__device__ int g_cnt[B_];
__device__ int g_local[M_];
__device__ int g_off[B_ + 2];        // [0..32] offsets; [32]=valid; [33]=padded
__device__ int g_rowidx[M_];

// ---------------- PTX helpers ------------------------------------------------
__device__ __forceinline__ uint32_t smem_u32(const void* p) {
    uint32_t a;
    asm("{ .reg .u64 t; cvta.to.shared.u64 t, %1; cvt.u32.u64 %0, t; }"
        : "=r"(a) : "l"(p));
    return a;
}
__device__ __forceinline__ void cp16(uint32_t dst, const void* src) {
    asm volatile("cp.async.cg.shared.global [%0], [%1], 16;" :: "r"(dst), "l"(src));
}
__device__ __forceinline__ void cp_commit() {
    asm volatile("cp.async.commit_group;" ::: "memory");
}
__device__ __forceinline__ void ldm_x4(uint32_t* r, uint32_t addr) {
    asm volatile("ldmatrix.sync.aligned.m8n8.x4.shared.b16 {%0,%1,%2,%3}, [%4];"
                 : "=r"(r[0]), "=r"(r[1]), "=r"(r[2]), "=r"(r[3]) : "r"(addr));
}
__device__ __forceinline__ void mma16816(float* c, const uint32_t* a, const uint32_t* b) {
    asm volatile(
        "mma.sync.aligned.m16n8k16.row.col.f32.bf16.bf16.f32 "
        "{%0,%1,%2,%3}, {%4,%5,%6,%7}, {%8,%9}, {%0,%1,%2,%3};"
        : "+f"(c[0]), "+f"(c[1]), "+f"(c[2]), "+f"(c[3])
        : "r"(a[0]), "r"(a[1]), "r"(a[2]), "r"(a[3]), "r"(b[0]), "r"(b[1]));
}

// ---------------- mask compaction -------------------------------------------
__global__ __launch_bounds__(Ls)
void mask_scan(const int* __restrict__ mask)
{
    const int b = blockIdx.x, l = threadIdx.x;
    const int lane = l & 31, w = l >> 5;
    const int v = mask[b * Ls + l] ? 1 : 0;
    const unsigned bal = __ballot_sync(0xffffffffu, v);
    const int pre = __popc(bal & ((1u << lane) - 1u));
    __shared__ int ws[16];
    if (lane == 0) ws[w] = __popc(bal);
    __syncthreads();
    int woff = 0;
#pragma unroll
    for (int i = 0; i < 16; i++) woff += (i < w) ? ws[i] : 0;
    g_local[b * Ls + l] = woff + pre;
    if (l == Ls - 1) g_cnt[b] = woff + pre + v;
}

__global__ void scan_offsets()
{
    const int t = threadIdx.x;            // 0..31
    int x = g_cnt[t];
#pragma unroll
    for (int o = 1; o < 32; o <<= 1) {
        int y = __shfl_up_sync(0xffffffffu, x, o);
        if (t >= o) x += y;
    }
    g_off[t + 1] = x;
    if (t == 0) g_off[0] = 0;
    if (t == 31) g_off[B_ + 1] = (x + 127) & ~127;   // padded total (TILE_M=128)
}

__global__ __launch_bounds__(Ls)
void scatter_idx(const int* __restrict__ mask)
{
    const int b = blockIdx.x, l = threadIdx.x;
    if (mask[b * Ls + l])
        g_rowidx[g_off[b] + g_local[b * Ls + l]] = b * Ls + l;
}

// ---------------- merged split: Q rows (gather, 1/temp) + P rows -----------
// blocks [0, M_)          : compact Q row  -> g_Qh / g_Ql
// blocks [M_, M_ + Kp)    : P row          -> g_Ph / g_Pl
__global__ __launch_bounds__(256)
void split_all(const float* __restrict__ Q, const float* __restrict__ P,
               const float* __restrict__ temp)
{
    const int blk = blockIdx.x;
    const int tid = threadIdx.x;

    if (blk < M_) {
        const int cr = blk;
        const int valid  = g_off[B_];
        const int padded = g_off[B_ + 1];
        if (cr >= padded) return;
        __nv_bfloat16* hp = g_Qh + (size_t)cr * D_;
        __nv_bfloat16* lp = g_Ql + (size_t)cr * D_;
        if (cr >= valid) {
#pragma unroll
            for (int j = 0; j < 3; j++) {
                hp[tid + j * 256] = __float2bfloat16(0.f);
                lp[tid + j * 256] = __float2bfloat16(0.f);
            }
            return;
        }
        const float invT = 1.0f / temp[0];
        const float* src = Q + (size_t)g_rowidx[cr] * D_;
#pragma unroll
        for (int j = 0; j < 3; j++) {
            float v = src[tid + j * 256] * invT;
            __nv_bfloat16 h = __float2bfloat16(v);
            hp[tid + j * 256] = h;
            lp[tid + j * 256] = __float2bfloat16(v - __bfloat162float(h));
        }
    } else {
        const int pr = blk - M_;                 // P row 0..Kp-1
        const float* src = P + (size_t)pr * D_;
        __nv_bfloat16* hp = g_Ph + (size_t)pr * D_;
        __nv_bfloat16* lp = g_Pl + (size_t)pr * D_;
#pragma unroll
        for (int j = 0; j < 3; j++) {
            float v = src[tid + j * 256];
            __nv_bfloat16 h = __float2bfloat16(v);
            hp[tid + j * 256] = h;
            lp[tid + j * 256] = __float2bfloat16(v - __bfloat162float(h));
        }
    }
}

// ---------------- HMMA GEMM (R7 proven config, untouched) -------------------
#define TILE_M 128
#define TILE_N 128
#define BK     32
#define CHUNKS (D_ / BK)       // 24
#define RSTRIDE 40
#define ROWB    (RSTRIDE * 2)
#define TILE_BYTES (128 * ROWB)             // 10240
#define STAGE_BYTES (4 * TILE_BYTES)        // Ah, Al, Bh, Bl
#define SMEM_GEMM   (2 * STAGE_BYTES)       // 81920

__global__ __launch_bounds__(256, 2)
void gemm_mma()
{
    if (blockIdx.x * TILE_M >= g_off[B_ + 1]) return;

    extern __shared__ __align__(16) char smem[];
    const uint32_t sb = smem_u32(smem);

    const int tid  = threadIdx.x;
    const int wid  = tid >> 5, lane = tid & 31;
    const int wm   = wid & 1;
    const int wn   = wid >> 1;
    const int m0   = blockIdx.x * TILE_M;
    const int n0   = blockIdx.y * TILE_N;

    auto load_chunk = [&](int c) {
        const uint32_t stage = sb + (uint32_t)(c & 1) * STAGE_BYTES;
        const int kd0 = c * BK;
#pragma unroll
        for (int it = 0; it < 8; it++) {
            int i    = tid + it * 256;
            int tile = i >> 9;                  // 0:Ah 1:Al 2:Bh 3:Bl
            int r    = (i >> 2) & 127;
            int q    = i & 3;
            uint32_t dst = stage + (uint32_t)tile * TILE_BYTES + r * ROWB + q * 16;
            size_t ge = (size_t)((tile < 2 ? m0 : n0) + r) * D_ + kd0 + q * 8;
            const __nv_bfloat16* src =
                tile == 0 ? g_Qh : tile == 1 ? g_Ql : tile == 2 ? g_Ph : g_Pl;
            cp16(dst, src + ge);
        }
        cp_commit();
    };

    float acc[4][4][4];
#pragma unroll
    for (int i = 0; i < 4; i++)
#pragma unroll
        for (int j = 0; j < 4; j++)
#pragma unroll
            for (int v = 0; v < 4; v++) acc[i][j][v] = 0.f;

    load_chunk(0);
    load_chunk(1);

    for (int c = 0; c < CHUNKS; c++) {
        if (c + 1 < CHUNKS)
            asm volatile("cp.async.wait_group 1;" ::: "memory");
        else
            asm volatile("cp.async.wait_group 0;" ::: "memory");
        __syncthreads();

        const uint32_t stage = sb + (uint32_t)(c & 1) * STAGE_BYTES;
        const uint32_t Ah = stage;
        const uint32_t Al = stage + TILE_BYTES;
        const uint32_t Bh = stage + 2 * TILE_BYTES;
        const uint32_t Bl = stage + 3 * TILE_BYTES;

#pragma unroll
        for (int k16 = 0; k16 < BK; k16 += 16) {
            uint32_t boff = (uint32_t)((wn * 32 + ((lane >> 4) << 3) + (lane & 7)) * ROWB
                                       + (k16 + (((lane >> 3) & 1) << 3)) * 2);
            uint32_t bh[8], bl[8];
            ldm_x4(&bh[0], Bh + boff);
            ldm_x4(&bh[4], Bh + boff + 16 * ROWB);
            ldm_x4(&bl[0], Bl + boff);
            ldm_x4(&bl[4], Bl + boff + 16 * ROWB);

            uint32_t aoff = (uint32_t)((wm * 64 + (lane & 15)) * ROWB
                                       + (k16 + ((lane >> 4) << 3)) * 2);
#pragma unroll
            for (int mt = 0; mt < 4; mt++) {
                uint32_t ah[4], al[4];
                ldm_x4(ah, Ah + aoff + mt * 16 * ROWB);
                ldm_x4(al, Al + aoff + mt * 16 * ROWB);
#pragma unroll
                for (int nt = 0; nt < 4; nt++) {
                    mma16816(acc[mt][nt], ah, &bh[nt * 2]);
                    mma16816(acc[mt][nt], ah, &bl[nt * 2]);
                    mma16816(acc[mt][nt], al, &bh[nt * 2]);
                }
            }
        }
        __syncthreads();
        if (c + 2 < CHUNKS) load_chunk(c + 2);
    }

    const int rbase = m0 + wm * 64 + (lane >> 2);
    const int cbase = n0 + wn * 32 + (lane & 3) * 2;
#pragma unroll
    for (int mt = 0; mt < 4; mt++) {
#pragma unroll
        for (int nt = 0; nt < 4; nt++) {
            float* p0 = &g_logits[(size_t)(rbase + mt * 16) * Kp + cbase + nt * 8];
            float* p1 = &g_logits[(size_t)(rbase + mt * 16 + 8) * Kp + cbase + nt * 8];
            *reinterpret_cast<float2*>(p0) = make_float2(acc[mt][nt][0], acc[mt][nt][1]);
            *reinterpret_cast<float2*>(p1) = make_float2(acc[mt][nt][2], acc[mt][nt][3]);
        }
    }
}

// ---------------- single-pass online row stats: c = m + log(sum exp) --------
__global__ __launch_bounds__(256)
void row_stats()
{
    const int row = blockIdx.x;
    if (row >= g_off[B_]) return;
    const float* Lr = g_logits + (size_t)row * Kp;
    const int tid = threadIdx.x;

    float m = -INFINITY, s = 0.f;
#pragma unroll
    for (int j = 0; j < 8; j++) {
        float4 v = *reinterpret_cast<const float4*>(&Lr[(tid + j * 256) * 4]);
        float lm = fmaxf(fmaxf(v.x, v.y), fmaxf(v.z, v.w));
        if (lm > m) { s *= expf(m - lm); m = lm; }
        s += expf(v.x - m) + expf(v.y - m) + expf(v.z - m) + expf(v.w - m);
    }
#pragma unroll
    for (int off = 16; off; off >>= 1) {
        float om = __shfl_xor_sync(0xffffffffu, m, off);
        float os = __shfl_xor_sync(0xffffffffu, s, off);
        float nm = fmaxf(m, om);
        s = s * expf(m - nm) + os * expf(om - nm);
        m = nm;
    }
    __shared__ float shm[8], shs[8];
    if ((tid & 31) == 0) { shm[tid >> 5] = m; shs[tid >> 5] = s; }
    __syncthreads();
    if (tid == 0) {
        float fm = shm[0], fs = shs[0];
#pragma unroll
        for (int w = 1; w < 8; w++) {
            float nm = fmaxf(fm, shm[w]);
            fs = fs * expf(fm - nm) + shs[w] * expf(shm[w] - nm);
            fm = nm;
        }
        g_c[row] = fm + logf(fs);
    }
}

// ---------------- column max over valid rows, exp into out ------------------
__global__ __launch_bounds__(256)
void col_max(float* __restrict__ out)
{
    const int b   = blockIdx.y;
    const int k   = blockIdx.x * 256 + threadIdx.x;
    const int tid = threadIdx.x;
    const int lo  = g_off[b], hi = g_off[b + 1];
    const int cnt = hi - lo;

    __shared__ float cs[Ls];
    for (int i = tid; i < cnt; i += 256) cs[i] = g_c[lo + i];
    __syncthreads();

    const float* base = g_logits + (size_t)lo * Kp + k;
    float t = -INFINITY;
    for (int i = 0; i < cnt; i++)
        t = fmaxf(t, base[(size_t)i * Kp] - cs[i]);

    out[b * Kp + k] = (cnt > 0) ? expf(t) : 0.f;
}

// ---------------- L2 normalize ----------------------------------------------
__device__ __forceinline__ float warpSum(float v) {
#pragma unroll
    for (int o = 16; o; o >>= 1) v += __shfl_xor_sync(0xffffffffu, v, o);
    return v;
}

__global__ __launch_bounds__(256)
void l2norm(float* __restrict__ out)
{
    const int b = blockIdx.x;
    float* o = out + b * Kp;
    const int tid = threadIdx.x;
    __shared__ float sh[8];
    __shared__ float bc;

    float s = 0.f;
    for (int i = tid; i < Kp; i += 256) { float v = o[i]; s = fmaf(v, v, s); }
    s = warpSum(s);
    if ((tid & 31) == 0) sh[tid >> 5] = s;
    __syncthreads();
    if (tid == 0) {
        float t = 0.f;
#pragma unroll
        for (int w = 0; w < 8; w++) t += sh[w];
        bc = 1.0f / fmaxf(sqrtf(t), 1e-12f);
    }
    __syncthreads();
    const float sc = bc;
    for (int i = tid; i < Kp; i += 256) o[i] *= sc;
}

// ---------------- launch (single stream, R7 structure) ----------------------
extern "C" void kernel_launch(void* const* d_in, const int* in_sizes, int n_in,
                              void* d_out, int out_size)
{
    const float* Q    = (const float*)d_in[0];
    const float* P    = (const float*)d_in[1];
    const float* temp = (const float*)d_in[2];
    const int*   mask = (const int*)d_in[3];
    float* out = (float*)d_out;

    cudaFuncSetAttribute(gemm_mma, cudaFuncAttributeMaxDynamicSharedMemorySize,
                         SMEM_GEMM);

    mask_scan<<<B_, Ls>>>(mask);
    scan_offsets<<<1, 32>>>();
    scatter_idx<<<B_, Ls>>>(mask);

    split_all<<<M_ + Kp, 256>>>(Q, P, temp);     // Q rows + P rows in one grid

    dim3 gGemm(M_ / TILE_M, Kp / TILE_N);        // (128, 64); empty m-tiles exit
    gemm_mma<<<gGemm, 256, SMEM_GEMM>>>();

    row_stats<<<M_, 256>>>();
    dim3 gCol(Kp / 256, B_);
    col_max<<<gCol, 256>>>(out);
    l2norm<<<B_, 256>>>(out);
}